// round 14
// baseline (speedup 1.0000x reference)
#include <cuda_runtime.h>
#include <cuda_fp16.h>
#include <math.h>
#include <stdint.h>

// ---------------- Problem constants ----------------
#define T_TOKENS 16384
#define D_MODEL  4096
#define N_EXP    128

// ---------------- GEMM config ----------------
#define BM   128
#define BN   128
#define CK   64                 // K per chunk (64 fp16 = 128B row)
#define NCHUNK (D_MODEL / CK)   // 64
#define TPB  640                // 16 consumer warps (4x4) + 4 producer warps

// smem: two 64KB stages; each: Ah Al Bh Bl (16KB each, 128 rows x 128B)
#define STAGE_BYTES 65536
#define OFF_AH 0
#define OFF_AL 16384
#define OFF_BH 32768
#define OFF_BL 49152
#define SMEM_TOTAL (2 * STAGE_BYTES)   // 131072

#define LS_STRIDE 132
#define SWZ(b) ((b) ^ (((b) >> 3) & 0x70))

// Named barriers (count = all 640 threads)
#define BAR_FULL0  1
#define BAR_FULL1  2
#define BAR_EMPTY0 3
#define BAR_EMPTY1 4
#define BAR_SYNC(id)   asm volatile("bar.sync %0, %1;"   :: "r"(id), "r"(TPB) : "memory")
#define BAR_ARRIVE(id) asm volatile("bar.arrive %0, %1;" :: "r"(id), "r"(TPB) : "memory")

// ---------------- sm_80-level PTX helpers ----------------
__device__ __forceinline__ uint32_t smem_to_u32(const void* p) {
    uint32_t a;
    asm("{ .reg .u64 t; cvta.to.shared.u64 t, %1; cvt.u32.u64 %0, t; }"
        : "=r"(a) : "l"(p));
    return a;
}
#define LDSM4(r0, r1, r2, r3, addr) \
    asm volatile("ldmatrix.sync.aligned.m8n8.x4.shared.b16 {%0,%1,%2,%3}, [%4];" \
        : "=r"(r0), "=r"(r1), "=r"(r2), "=r"(r3) : "r"(addr))
#define MMA16816(c, a, b0, b1) \
    asm volatile("mma.sync.aligned.m16n8k16.row.col.f32.f16.f16.f32 " \
        "{%0,%1,%2,%3},{%4,%5,%6,%7},{%8,%9},{%0,%1,%2,%3};" \
        : "+f"((c)[0]), "+f"((c)[1]), "+f"((c)[2]), "+f"((c)[3]) \
        : "r"((a)[0]), "r"((a)[1]), "r"((a)[2]), "r"((a)[3]), "r"(b0), "r"(b1))
#define MMA16816_H(c, a, b0, b1) \
    asm volatile("mma.sync.aligned.m16n8k16.row.col.f16.f16.f16.f16 " \
        "{%0,%1},{%2,%3,%4,%5},{%6,%7},{%0,%1};" \
        : "+r"((c)[0]), "+r"((c)[1]) \
        : "r"((a)[0]), "r"((a)[1]), "r"((a)[2]), "r"((a)[3]), "r"(b0), "r"(b1))

// ---------------- Global scratch ----------------
__device__ float g_me[N_EXP];
__device__ int   g_ce[N_EXP];
__device__ unsigned int g_done;

// fp16 2-way split, UNSCALED residual: f = h + l (l may be subnormal)
__device__ __forceinline__ void split2(float f, __half& h, __half& l) {
    h = __float2half_rn(f);
    l = __float2half_rn(f - __half2float(h));
}
__device__ __forceinline__ uint32_t pack2h(__half a, __half b) {
    return (uint32_t)__half_as_ushort(a) |
           ((uint32_t)__half_as_ushort(b) << 16);
}

// top-2: (v1,i1) >= (v2,i2); ties -> smaller index (jax top_k semantics)
__device__ __forceinline__ void top2_upd(float& v1, int& i1, float& v2, int& i2,
                                         float v, int i) {
    if (v > v1 || (v == v1 && i < i1)) {
        v2 = v1; i2 = i1; v1 = v; i1 = i;
    } else if (v > v2 || (v == v2 && i < i2)) {
        v2 = v; i2 = i;
    }
}

// Producer tile fill: 128 rows x 64 fp32 -> h/l fp16 tiles (SW128), 16 float4/thread
__device__ __forceinline__ void fill_tile(char* stg, int off_h, int off_l,
                                          const float* __restrict__ src,
                                          int ptid) {
#pragma unroll
    for (int bat = 0; bat < 2; bat++) {
        float4 aval[8];
#pragma unroll
        for (int j = 0; j < 8; j++) {
            int idx = ptid + (bat * 8 + j) * 128;   // 0..2047
            int r   = idx >> 4;
            int col = (idx & 15) << 2;
            aval[j] = *(const float4*)(src + (size_t)r * D_MODEL + col);
        }
#pragma unroll
        for (int j = 0; j < 8; j++) {
            int idx = ptid + (bat * 8 + j) * 128;
            int r   = idx >> 4;
            int col = (idx & 15) << 2;
            float f[4] = {aval[j].x, aval[j].y, aval[j].z, aval[j].w};
            __half h[4], l[4];
#pragma unroll
            for (int q = 0; q < 4; q++) split2(f[q], h[q], l[q]);
            uint32_t sw = SWZ((uint32_t)(r * 128 + col * 2));
            *(uint2*)(stg + off_h + sw) = make_uint2(pack2h(h[0], h[1]), pack2h(h[2], h[3]));
            *(uint2*)(stg + off_l + sw) = make_uint2(pack2h(l[0], l[1]), pack2h(l[2], l[3]));
        }
    }
}

__global__ void __launch_bounds__(TPB, 1)
gate_kernel(const float* __restrict__ A, const float* __restrict__ Wg,
            float* __restrict__ out) {
    extern __shared__ char smem[];
    const uint32_t smem_u = smem_to_u32(smem);
    const int tid  = threadIdx.x;
    const int wid  = tid >> 5;
    const int lane = tid & 31;
    const int row0 = blockIdx.x * BM;

    float    acc[2][4][4];    // hh product, f32
    uint32_t accr[2][4][2];   // residual products, f16x2 pairs

    if (wid < 16) {
        // ================= CONSUMERS: 4(M) x 4(N) warp grid =================
        const int mw = wid >> 2;
        const int nw = wid & 3;
        const int a_mrow = (lane & 7) + ((lane >> 3) & 1) * 8;
        const int a_cofs = ((lane >> 4) & 1) * 16;
        const int b_nrow = (lane & 7) + ((lane >> 4) & 1) * 8;
        const int b_cofs = ((lane >> 3) & 1) * 16;

#pragma unroll
        for (int i = 0; i < 2; i++)
#pragma unroll
            for (int j = 0; j < 4; j++) {
#pragma unroll
                for (int q = 0; q < 4; q++) acc[i][j][q] = 0.0f;
                accr[i][j][0] = 0u; accr[i][j][1] = 0u;
            }

        for (int c = 0; c < NCHUNK; c++) {
            const int s = c & 1;
            const uint32_t cur = smem_u + s * STAGE_BYTES;
            BAR_SYNC(s == 0 ? BAR_FULL0 : BAR_FULL1);

#pragma unroll 1
            for (int ks = 0; ks < 4; ks++) {
                const int kb = ks * 32;
                uint32_t bfh[8], bfl[8];
#pragma unroll
                for (int q = 0; q < 2; q++) {
                    uint32_t bsw = SWZ((uint32_t)((nw * 32 + q * 16 + b_nrow) * 128 + kb + b_cofs));
                    LDSM4(bfh[q*4+0], bfh[q*4+1], bfh[q*4+2], bfh[q*4+3], cur + OFF_BH + bsw);
                    LDSM4(bfl[q*4+0], bfl[q*4+1], bfl[q*4+2], bfl[q*4+3], cur + OFF_BL + bsw);
                }
                uint32_t af[8];
#pragma unroll
                for (int tm = 0; tm < 2; tm++) {
                    uint32_t asw = SWZ((uint32_t)((mw * 32 + tm * 16 + a_mrow) * 128 + kb + a_cofs));
                    LDSM4(af[tm*4+0], af[tm*4+1], af[tm*4+2], af[tm*4+3], cur + OFF_AH + asw);
                }
#pragma unroll
                for (int tm = 0; tm < 2; tm++)
#pragma unroll
                    for (int tn = 0; tn < 4; tn++) {
                        int bq = (tn >> 1) * 4 + (tn & 1) * 2;
                        MMA16816(acc[tm][tn], &af[tm*4], bfh[bq], bfh[bq+1]);
                        MMA16816_H(accr[tm][tn], &af[tm*4], bfl[bq], bfl[bq+1]);
                    }
#pragma unroll
                for (int tm = 0; tm < 2; tm++) {
                    uint32_t asw = SWZ((uint32_t)((mw * 32 + tm * 16 + a_mrow) * 128 + kb + a_cofs));
                    LDSM4(af[tm*4+0], af[tm*4+1], af[tm*4+2], af[tm*4+3], cur + OFF_AL + asw);
                }
#pragma unroll
                for (int tm = 0; tm < 2; tm++)
#pragma unroll
                    for (int tn = 0; tn < 4; tn++) {
                        int bq = (tn >> 1) * 4 + (tn & 1) * 2;
                        MMA16816_H(accr[tm][tn], &af[tm*4], bfh[bq], bfh[bq+1]);
                    }
            }
            BAR_ARRIVE(s == 0 ? BAR_EMPTY0 : BAR_EMPTY1);
        }
    } else {
        // ============ PRODUCERS: 4 warps; split BOTH A and B from fp32 ======
        const int ptid = tid - 512;   // 0..127
        for (int c = 0; c < NCHUNK; c++) {
            const int s = c & 1;
            char* stg = smem + s * STAGE_BYTES;
            const int k0 = c * CK;

            if (c >= 2) BAR_SYNC(s == 0 ? BAR_EMPTY0 : BAR_EMPTY1);

            fill_tile(stg, OFF_BH, OFF_BL, Wg + k0, ptid);                       // B tile
            fill_tile(stg, OFF_AH, OFF_AL, A + (size_t)row0 * D_MODEL + k0, ptid); // A tile

            BAR_ARRIVE(s == 0 ? BAR_FULL0 : BAR_FULL1);
        }
    }

    __syncthreads();   // all 640 threads; stages now free -> repurpose as Ls

    float* Ls  = (float*)smem;
    float* sMe = (float*)(smem + BM * LS_STRIDE * 4);

    if (wid < 16) {
        const int mw = wid >> 2, nw = wid & 3;
        const int gid = lane >> 2, tig = lane & 3;
#pragma unroll
        for (int tm = 0; tm < 2; tm++)
#pragma unroll
            for (int tn = 0; tn < 4; tn++) {
                float2 rlo = __half22float2(*(__half2*)&accr[tm][tn][0]);
                float2 rhi = __half22float2(*(__half2*)&accr[tm][tn][1]);
                int r_ = mw * 32 + tm * 16 + gid;
                int c_ = nw * 32 + tn * 8 + tig * 2;
                Ls[r_ * LS_STRIDE + c_]           = acc[tm][tn][0] + rlo.x;
                Ls[r_ * LS_STRIDE + c_ + 1]       = acc[tm][tn][1] + rlo.y;
                Ls[(r_ + 8) * LS_STRIDE + c_]     = acc[tm][tn][2] + rhi.x;
                Ls[(r_ + 8) * LS_STRIDE + c_ + 1] = acc[tm][tn][3] + rhi.y;
            }
    }
    if (tid >= 512 && tid < 512 + N_EXP) sMe[tid - 512] = 0.0f;
    __syncthreads();

    // ---- epilogue: one warp per token, 20 warps stride over 128 tokens ----
    const float inv_temp = 1.0f / 0.3f;
    for (int t = wid; t < BM; t += 20) {
        float v[4]; int ix[4];
#pragma unroll
        for (int q = 0; q < 4; q++) {
            ix[q] = lane + q * 32;
            v[q]  = Ls[t * LS_STRIDE + ix[q]];
        }
        float v1 = -INFINITY, v2 = -INFINITY;
        int   i1 = N_EXP, i2 = N_EXP;
#pragma unroll
        for (int q = 0; q < 4; q++) top2_upd(v1, i1, v2, i2, v[q], ix[q]);
#pragma unroll
        for (int off = 16; off > 0; off >>= 1) {
            float ov1 = __shfl_xor_sync(0xffffffffu, v1, off);
            int   oi1 = __shfl_xor_sync(0xffffffffu, i1, off);
            float ov2 = __shfl_xor_sync(0xffffffffu, v2, off);
            int   oi2 = __shfl_xor_sync(0xffffffffu, i2, off);
            top2_upd(v1, i1, v2, i2, ov1, oi1);
            top2_upd(v1, i1, v2, i2, ov2, oi2);
        }
        float p[4], zl = 0.0f;
#pragma unroll
        for (int q = 0; q < 4; q++) {
            p[q] = expf((v[q] - v1) * inv_temp);
            zl += p[q];
        }
#pragma unroll
        for (int off = 16; off > 0; off >>= 1)
            zl += __shfl_xor_sync(0xffffffffu, zl, off);
        float invZ = 1.0f / zl;
#pragma unroll
        for (int q = 0; q < 4; q++)
            atomicAdd(&sMe[ix[q]], p[q] * invZ);

        if (lane == 0) {
            int tok = row0 + t;
            out[tok * 2 + 0] = (float)i1;
            out[tok * 2 + 1] = (float)i2;
            float e  = expf(v2 - v1);
            float g1 = e / (1.0f + e);
            out[2 * T_TOKENS + tok * 2 + 0] = 1.0f - g1;
            out[2 * T_TOKENS + tok * 2 + 1] = g1;
            atomicAdd(&g_ce[i1], 1);
        }
    }
    __syncthreads();
    if (tid < N_EXP) atomicAdd(&g_me[tid], sMe[tid]);

    // ---- last-CTA loss reduction (replaces loss_kernel launch) ----
    __threadfence();
    __syncthreads();
    unsigned int* flag = (unsigned int*)smem;
    if (tid == 0) {
        unsigned int prev = atomicAdd(&g_done, 1u);
        *flag = (prev == gridDim.x - 1) ? 1u : 0u;
    }
    __syncthreads();
    if (*flag) {
        float* red = (float*)(smem + 64);
        if (tid < N_EXP)
            red[tid] = __ldcg(&g_me[tid]) * (float)__ldcg(&g_ce[tid]);
        __syncthreads();
        for (int s = 64; s > 0; s >>= 1) {
            if (tid < s) red[tid] += red[tid + s];
            __syncthreads();
        }
        if (tid == 0)
            out[4 * T_TOKENS] = red[0] * ((float)N_EXP /
                                  ((float)T_TOKENS * (float)T_TOKENS));
    }
}

extern "C" void kernel_launch(void* const* d_in, const int* in_sizes, int n_in,
                              void* d_out, int out_size) {
    const float* inp = (const float*)d_in[0];
    const float* wg  = (const float*)d_in[1];
    float* out = (float*)d_out;

    void *p_me = nullptr, *p_ce = nullptr, *p_done = nullptr;
    cudaGetSymbolAddress(&p_me, g_me);
    cudaGetSymbolAddress(&p_ce, g_ce);
    cudaGetSymbolAddress(&p_done, g_done);
    cudaMemsetAsync(p_me, 0, N_EXP * sizeof(float));
    cudaMemsetAsync(p_ce, 0, N_EXP * sizeof(int));
    cudaMemsetAsync(p_done, 0, sizeof(unsigned int));

    cudaFuncSetAttribute(gate_kernel,
                         cudaFuncAttributeMaxDynamicSharedMemorySize,
                         SMEM_TOTAL);
    gate_kernel<<<T_TOKENS / BM, TPB, SMEM_TOTAL>>>(inp, wg, out);
}

// round 15
// speedup vs baseline: 1.3845x; 1.3845x over previous
#include <cuda_runtime.h>
#include <cuda_fp16.h>
#include <math.h>
#include <stdint.h>

// ---------------- Problem constants ----------------
#define T_TOKENS 16384
#define D_MODEL  4096
#define N_EXP    128

// ---------------- GEMM config ----------------
#define BM   128
#define BN   128
#define CK   64                 // K per chunk (64 fp16 = 128B row)
#define NCHUNK (D_MODEL / CK)   // 64
#define TPB  640                // 16 consumer warps (4x4) + 4 producer warps

// smem: two 64KB stages; each: Ah Al Bh Bl (16KB each, 128 rows x 128B)
#define STAGE_BYTES 65536
#define OFF_AH 0
#define OFF_AL 16384
#define OFF_BH 32768
#define OFF_BL 49152
#define SMEM_TOTAL (2 * STAGE_BYTES)   // 131072

#define LS_STRIDE 132
#define SWZ(b) ((b) ^ (((b) >> 3) & 0x70))

// Named barriers (count = all 640 threads)
#define BAR_FULL0  1
#define BAR_FULL1  2
#define BAR_EMPTY0 3
#define BAR_EMPTY1 4
#define BAR_SYNC(id)   asm volatile("bar.sync %0, %1;"   :: "r"(id), "r"(TPB) : "memory")
#define BAR_ARRIVE(id) asm volatile("bar.arrive %0, %1;" :: "r"(id), "r"(TPB) : "memory")

// ---------------- sm_80-level PTX helpers ----------------
__device__ __forceinline__ uint32_t smem_to_u32(const void* p) {
    uint32_t a;
    asm("{ .reg .u64 t; cvta.to.shared.u64 t, %1; cvt.u32.u64 %0, t; }"
        : "=r"(a) : "l"(p));
    return a;
}
#define LDSM4(r0, r1, r2, r3, addr) \
    asm volatile("ldmatrix.sync.aligned.m8n8.x4.shared.b16 {%0,%1,%2,%3}, [%4];" \
        : "=r"(r0), "=r"(r1), "=r"(r2), "=r"(r3) : "r"(addr))
// f32-accumulator MMA (for the hh product)
#define MMA16816(c, a, b0, b1) \
    asm volatile("mma.sync.aligned.m16n8k16.row.col.f32.f16.f16.f32 " \
        "{%0,%1,%2,%3},{%4,%5,%6,%7},{%8,%9},{%0,%1,%2,%3};" \
        : "+f"((c)[0]), "+f"((c)[1]), "+f"((c)[2]), "+f"((c)[3]) \
        : "r"((a)[0]), "r"((a)[1]), "r"((a)[2]), "r"((a)[3]), "r"(b0), "r"(b1))
// f16-accumulator MMA (for the small residual products)
#define MMA16816_H(c, a, b0, b1) \
    asm volatile("mma.sync.aligned.m16n8k16.row.col.f16.f16.f16.f16 " \
        "{%0,%1},{%2,%3,%4,%5},{%6,%7},{%0,%1};" \
        : "+r"((c)[0]), "+r"((c)[1]) \
        : "r"((a)[0]), "r"((a)[1]), "r"((a)[2]), "r"((a)[3]), "r"(b0), "r"(b1))
__device__ __forceinline__ void cp16(uint32_t dst, const void* src) {
    asm volatile("cp.async.cg.shared.global [%0], [%1], 16;"
                 :: "r"(dst), "l"(src));
}
#define CP_COMMIT() asm volatile("cp.async.commit_group;" ::: "memory")
#define CP_WAIT0()  asm volatile("cp.async.wait_group 0;" ::: "memory")

// ---------------- Global scratch ----------------
__device__ float g_me[N_EXP];
__device__ int   g_ce[N_EXP];
__device__ unsigned int g_done;
__device__ __half g_Bh[N_EXP * D_MODEL];
__device__ __half g_Bl[N_EXP * D_MODEL];

// fp16 2-way split, UNSCALED residual: f = h + l (l may be subnormal)
__device__ __forceinline__ void split2(float f, __half& h, __half& l) {
    h = __float2half_rn(f);
    l = __float2half_rn(f - __half2float(h));
}
__device__ __forceinline__ uint32_t pack2h(__half a, __half b) {
    return (uint32_t)__half_as_ushort(a) |
           ((uint32_t)__half_as_ushort(b) << 16);
}

// prep: split wg into fp16 h/l globals (one-time, 512x256 threads)
__global__ void prep_b_kernel(const float* __restrict__ wg) {
    int idx = blockIdx.x * blockDim.x + threadIdx.x;  // 0..131071
    float4 v = ((const float4*)wg)[idx];
    float f[4] = {v.x, v.y, v.z, v.w};
    __half h[4], l[4];
#pragma unroll
    for (int q = 0; q < 4; q++) split2(f[q], h[q], l[q]);
    ((uint2*)g_Bh)[idx] = make_uint2(pack2h(h[0], h[1]), pack2h(h[2], h[3]));
    ((uint2*)g_Bl)[idx] = make_uint2(pack2h(l[0], l[1]), pack2h(l[2], l[3]));
}

// top-2: (v1,i1) >= (v2,i2); ties -> smaller index (jax top_k semantics)
__device__ __forceinline__ void top2_upd(float& v1, int& i1, float& v2, int& i2,
                                         float v, int i) {
    if (v > v1 || (v == v1 && i < i1)) {
        v2 = v1; i2 = i1; v1 = v; i1 = i;
    } else if (v > v2 || (v == v2 && i < i2)) {
        v2 = v; i2 = i;
    }
}

__global__ void __launch_bounds__(TPB, 1)
gate_kernel(const float* __restrict__ A, float* __restrict__ out) {
    extern __shared__ char smem[];
    const uint32_t smem_u = smem_to_u32(smem);
    const int tid  = threadIdx.x;
    const int wid  = tid >> 5;
    const int lane = tid & 31;
    const int row0 = blockIdx.x * BM;

    float    acc[2][4][4];    // hh product, f32
    uint32_t accr[2][4][2];   // residual products, f16x2 pairs

    if (wid < 16) {
        // ================= CONSUMERS: 4(M) x 4(N) warp grid =================
        const int mw = wid >> 2;
        const int nw = wid & 3;
        const int a_mrow = (lane & 7) + ((lane >> 3) & 1) * 8;
        const int a_cofs = ((lane >> 4) & 1) * 16;
        const int b_nrow = (lane & 7) + ((lane >> 4) & 1) * 8;
        const int b_cofs = ((lane >> 3) & 1) * 16;

#pragma unroll
        for (int i = 0; i < 2; i++)
#pragma unroll
            for (int j = 0; j < 4; j++) {
#pragma unroll
                for (int q = 0; q < 4; q++) acc[i][j][q] = 0.0f;
                accr[i][j][0] = 0u; accr[i][j][1] = 0u;
            }

        for (int c = 0; c < NCHUNK; c++) {
            const int s = c & 1;
            const uint32_t cur = smem_u + s * STAGE_BYTES;
            BAR_SYNC(s == 0 ? BAR_FULL0 : BAR_FULL1);

#pragma unroll 1
            for (int ks = 0; ks < 4; ks++) {
                const int kb = ks * 32;
                uint32_t bfh[8], bfl[8];
#pragma unroll
                for (int q = 0; q < 2; q++) {
                    uint32_t bsw = SWZ((uint32_t)((nw * 32 + q * 16 + b_nrow) * 128 + kb + b_cofs));
                    LDSM4(bfh[q*4+0], bfh[q*4+1], bfh[q*4+2], bfh[q*4+3], cur + OFF_BH + bsw);
                    LDSM4(bfl[q*4+0], bfl[q*4+1], bfl[q*4+2], bfl[q*4+3], cur + OFF_BL + bsw);
                }
                uint32_t af[8];
#pragma unroll
                for (int tm = 0; tm < 2; tm++) {
                    uint32_t asw = SWZ((uint32_t)((mw * 32 + tm * 16 + a_mrow) * 128 + kb + a_cofs));
                    LDSM4(af[tm*4+0], af[tm*4+1], af[tm*4+2], af[tm*4+3], cur + OFF_AH + asw);
                }
#pragma unroll
                for (int tm = 0; tm < 2; tm++)
#pragma unroll
                    for (int tn = 0; tn < 4; tn++) {
                        int bq = (tn >> 1) * 4 + (tn & 1) * 2;
                        MMA16816(acc[tm][tn], &af[tm*4], bfh[bq], bfh[bq+1]);
                        MMA16816_H(accr[tm][tn], &af[tm*4], bfl[bq], bfl[bq+1]);
                    }
#pragma unroll
                for (int tm = 0; tm < 2; tm++) {
                    uint32_t asw = SWZ((uint32_t)((mw * 32 + tm * 16 + a_mrow) * 128 + kb + a_cofs));
                    LDSM4(af[tm*4+0], af[tm*4+1], af[tm*4+2], af[tm*4+3], cur + OFF_AL + asw);
                }
#pragma unroll
                for (int tm = 0; tm < 2; tm++)
#pragma unroll
                    for (int tn = 0; tn < 4; tn++) {
                        int bq = (tn >> 1) * 4 + (tn & 1) * 2;
                        MMA16816_H(accr[tm][tn], &af[tm*4], bfh[bq], bfh[bq+1]);
                    }
            }
            BAR_ARRIVE(s == 0 ? BAR_EMPTY0 : BAR_EMPTY1);
        }
    } else {
        // ================= PRODUCERS: 4 warps, 128 threads =================
        const int ptid = tid - 512;   // 0..127
        for (int c = 0; c < NCHUNK; c++) {
            const int s = c & 1;
            char* stg = smem + s * STAGE_BYTES;
            const uint32_t stg_u = smem_u + s * STAGE_BYTES;
            const int k0 = c * CK;

            if (c >= 2) BAR_SYNC(s == 0 ? BAR_EMPTY0 : BAR_EMPTY1);

            // B tiles via cp.async (in flight during A work)
#pragma unroll
            for (int i = 0; i < 8; i++) {
                int idx = ptid + i * 128;          // 0..1023
                int r   = idx >> 3;
                int c16 = (idx & 7) * 16;
                size_t g = (size_t)r * D_MODEL + k0 + (c16 >> 1);
                uint32_t sw = SWZ((uint32_t)(r * 128 + c16));
                cp16(stg_u + OFF_BH + sw, g_Bh + g);
                cp16(stg_u + OFF_BL + sw, g_Bl + g);
            }
            CP_COMMIT();

            // A: LDG -> split2 -> STS, 2 batches of 8 float4 (reg budget 102)
#pragma unroll
            for (int bat = 0; bat < 2; bat++) {
                float4 aval[8];
#pragma unroll
                for (int i = 0; i < 8; i++) {
                    int idx = ptid + (bat * 8 + i) * 128;   // 0..2047
                    int r   = idx >> 4;
                    int col = (idx & 15) << 2;
                    aval[i] = *(const float4*)(A + (size_t)(row0 + r) * D_MODEL + k0 + col);
                }
#pragma unroll
                for (int i = 0; i < 8; i++) {
                    int idx = ptid + (bat * 8 + i) * 128;
                    int r   = idx >> 4;
                    int col = (idx & 15) << 2;
                    float f[4] = {aval[i].x, aval[i].y, aval[i].z, aval[i].w};
                    __half h[4], l[4];
#pragma unroll
                    for (int q = 0; q < 4; q++) split2(f[q], h[q], l[q]);
                    uint32_t sw = SWZ((uint32_t)(r * 128 + col * 2));
                    *(uint2*)(stg + OFF_AH + sw) = make_uint2(pack2h(h[0], h[1]), pack2h(h[2], h[3]));
                    *(uint2*)(stg + OFF_AL + sw) = make_uint2(pack2h(l[0], l[1]), pack2h(l[2], l[3]));
                }
            }
            CP_WAIT0();
            BAR_ARRIVE(s == 0 ? BAR_FULL0 : BAR_FULL1);
        }
    }

    __syncthreads();   // all 640 threads; stages now free -> repurpose as Ls

    float* Ls  = (float*)smem;
    float* sMe = (float*)(smem + BM * LS_STRIDE * 4);

    if (wid < 16) {
        const int mw = wid >> 2, nw = wid & 3;
        const int gid = lane >> 2, tig = lane & 3;
#pragma unroll
        for (int tm = 0; tm < 2; tm++)
#pragma unroll
            for (int tn = 0; tn < 4; tn++) {
                float2 rlo = __half22float2(*(__half2*)&accr[tm][tn][0]);
                float2 rhi = __half22float2(*(__half2*)&accr[tm][tn][1]);
                int r_ = mw * 32 + tm * 16 + gid;
                int c_ = nw * 32 + tn * 8 + tig * 2;
                Ls[r_ * LS_STRIDE + c_]           = acc[tm][tn][0] + rlo.x;
                Ls[r_ * LS_STRIDE + c_ + 1]       = acc[tm][tn][1] + rlo.y;
                Ls[(r_ + 8) * LS_STRIDE + c_]     = acc[tm][tn][2] + rhi.x;
                Ls[(r_ + 8) * LS_STRIDE + c_ + 1] = acc[tm][tn][3] + rhi.y;
            }
    }
    if (tid >= 512 && tid < 512 + N_EXP) sMe[tid - 512] = 0.0f;
    __syncthreads();

    // ---- epilogue: one warp per token, 20 warps stride over 128 tokens ----
    const float inv_temp = 1.0f / 0.3f;
    for (int t = wid; t < BM; t += 20) {
        float v[4]; int ix[4];
#pragma unroll
        for (int q = 0; q < 4; q++) {
            ix[q] = lane + q * 32;
            v[q]  = Ls[t * LS_STRIDE + ix[q]];
        }
        float v1 = -INFINITY, v2 = -INFINITY;
        int   i1 = N_EXP, i2 = N_EXP;
#pragma unroll
        for (int q = 0; q < 4; q++) top2_upd(v1, i1, v2, i2, v[q], ix[q]);
#pragma unroll
        for (int off = 16; off > 0; off >>= 1) {
            float ov1 = __shfl_xor_sync(0xffffffffu, v1, off);
            int   oi1 = __shfl_xor_sync(0xffffffffu, i1, off);
            float ov2 = __shfl_xor_sync(0xffffffffu, v2, off);
            int   oi2 = __shfl_xor_sync(0xffffffffu, i2, off);
            top2_upd(v1, i1, v2, i2, ov1, oi1);
            top2_upd(v1, i1, v2, i2, ov2, oi2);
        }
        float p[4], zl = 0.0f;
#pragma unroll
        for (int q = 0; q < 4; q++) {
            p[q] = expf((v[q] - v1) * inv_temp);
            zl += p[q];
        }
#pragma unroll
        for (int off = 16; off > 0; off >>= 1)
            zl += __shfl_xor_sync(0xffffffffu, zl, off);
        float invZ = 1.0f / zl;
#pragma unroll
        for (int q = 0; q < 4; q++)
            atomicAdd(&sMe[ix[q]], p[q] * invZ);

        if (lane == 0) {
            int tok = row0 + t;
            out[tok * 2 + 0] = (float)i1;
            out[tok * 2 + 1] = (float)i2;
            float e  = expf(v2 - v1);
            float g1 = e / (1.0f + e);
            out[2 * T_TOKENS + tok * 2 + 0] = 1.0f - g1;
            out[2 * T_TOKENS + tok * 2 + 1] = g1;
            atomicAdd(&g_ce[i1], 1);
        }
    }
    __syncthreads();
    if (tid < N_EXP) atomicAdd(&g_me[tid], sMe[tid]);

    // ---- last-CTA loss reduction (replaces loss_kernel launch) ----
    __threadfence();
    __syncthreads();
    unsigned int* flag = (unsigned int*)smem;
    if (tid == 0) {
        unsigned int prev = atomicAdd(&g_done, 1u);
        *flag = (prev == gridDim.x - 1) ? 1u : 0u;
    }
    __syncthreads();
    if (*flag) {
        float* red = (float*)(smem + 64);
        if (tid < N_EXP)
            red[tid] = __ldcg(&g_me[tid]) * (float)__ldcg(&g_ce[tid]);
        __syncthreads();
        for (int s = 64; s > 0; s >>= 1) {
            if (tid < s) red[tid] += red[tid + s];
            __syncthreads();
        }
        if (tid == 0)
            out[4 * T_TOKENS] = red[0] * ((float)N_EXP /
                                  ((float)T_TOKENS * (float)T_TOKENS));
    }
}

extern "C" void kernel_launch(void* const* d_in, const int* in_sizes, int n_in,
                              void* d_out, int out_size) {
    const float* inp = (const float*)d_in[0];
    const float* wg  = (const float*)d_in[1];
    float* out = (float*)d_out;

    void *p_me = nullptr, *p_ce = nullptr, *p_done = nullptr;
    cudaGetSymbolAddress(&p_me, g_me);
    cudaGetSymbolAddress(&p_ce, g_ce);
    cudaGetSymbolAddress(&p_done, g_done);
    cudaMemsetAsync(p_me, 0, N_EXP * sizeof(float));
    cudaMemsetAsync(p_ce, 0, N_EXP * sizeof(int));
    cudaMemsetAsync(p_done, 0, sizeof(unsigned int));

    prep_b_kernel<<<(N_EXP * D_MODEL / 4 + 255) / 256, 256>>>(wg);

    cudaFuncSetAttribute(gate_kernel,
                         cudaFuncAttributeMaxDynamicSharedMemorySize,
                         SMEM_TOTAL);
    gate_kernel<<<T_TOKENS / BM, TPB, SMEM_TOTAL>>>(inp, out);
}

// round 16
// speedup vs baseline: 1.4143x; 1.0215x over previous
#include <cuda_runtime.h>
#include <cuda_fp16.h>
#include <math.h>
#include <stdint.h>

// ---------------- Problem constants ----------------
#define T_TOKENS 16384
#define D_MODEL  4096
#define N_EXP    128

// ---------------- GEMM config ----------------
#define BM   128
#define BN   128
#define CK   64                 // K per chunk (64 fp16 = 128B row)
#define NCHUNK (D_MODEL / CK)   // 64
#define TPB  640                // 16 consumer warps (4x4) + 4 producer warps

// smem: two 64KB stages; each: Ah Al Bh Bl (16KB each, 128 rows x 128B)
#define STAGE_BYTES 65536
#define OFF_AH 0
#define OFF_AL 16384
#define OFF_BH 32768
#define OFF_BL 49152
#define SMEM_TOTAL (2 * STAGE_BYTES)   // 131072

#define LS_STRIDE 132
#define SWZ(b) ((b) ^ (((b) >> 3) & 0x70))

// Named barriers (count = all 640 threads)
#define BAR_FULL0  1
#define BAR_FULL1  2
#define BAR_EMPTY0 3
#define BAR_EMPTY1 4
#define BAR_SYNC(id)   asm volatile("bar.sync %0, %1;"   :: "r"(id), "r"(TPB) : "memory")
#define BAR_ARRIVE(id) asm volatile("bar.arrive %0, %1;" :: "r"(id), "r"(TPB) : "memory")

// ---------------- sm_80-level PTX helpers ----------------
__device__ __forceinline__ uint32_t smem_to_u32(const void* p) {
    uint32_t a;
    asm("{ .reg .u64 t; cvta.to.shared.u64 t, %1; cvt.u32.u64 %0, t; }"
        : "=r"(a) : "l"(p));
    return a;
}
#define LDSM4(r0, r1, r2, r3, addr) \
    asm volatile("ldmatrix.sync.aligned.m8n8.x4.shared.b16 {%0,%1,%2,%3}, [%4];" \
        : "=r"(r0), "=r"(r1), "=r"(r2), "=r"(r3) : "r"(addr))
// f32-accumulator MMA (for the hh product)
#define MMA16816(c, a, b0, b1) \
    asm volatile("mma.sync.aligned.m16n8k16.row.col.f32.f16.f16.f32 " \
        "{%0,%1,%2,%3},{%4,%5,%6,%7},{%8,%9},{%0,%1,%2,%3};" \
        : "+f"((c)[0]), "+f"((c)[1]), "+f"((c)[2]), "+f"((c)[3]) \
        : "r"((a)[0]), "r"((a)[1]), "r"((a)[2]), "r"((a)[3]), "r"(b0), "r"(b1))
// f16-accumulator MMA (for the small residual products)
#define MMA16816_H(c, a, b0, b1) \
    asm volatile("mma.sync.aligned.m16n8k16.row.col.f16.f16.f16.f16 " \
        "{%0,%1},{%2,%3,%4,%5},{%6,%7},{%0,%1};" \
        : "+r"((c)[0]), "+r"((c)[1]) \
        : "r"((a)[0]), "r"((a)[1]), "r"((a)[2]), "r"((a)[3]), "r"(b0), "r"(b1))
__device__ __forceinline__ void cp16(uint32_t dst, const void* src) {
    asm volatile("cp.async.cg.shared.global [%0], [%1], 16;"
                 :: "r"(dst), "l"(src));
}
#define CP_COMMIT() asm volatile("cp.async.commit_group;" ::: "memory")
#define CP_WAIT0()  asm volatile("cp.async.wait_group 0;" ::: "memory")

// ---------------- Global scratch ----------------
__device__ float g_me[N_EXP];
__device__ int   g_ce[N_EXP];
__device__ unsigned int g_done;
__device__ __half g_Bh[N_EXP * D_MODEL];
__device__ __half g_Bl[N_EXP * D_MODEL];

// fp16 2-way split, UNSCALED residual: f = h + l (l may be subnormal)
__device__ __forceinline__ void split2(float f, __half& h, __half& l) {
    h = __float2half_rn(f);
    l = __float2half_rn(f - __half2float(h));
}
__device__ __forceinline__ uint32_t pack2h(__half a, __half b) {
    return (uint32_t)__half_as_ushort(a) |
           ((uint32_t)__half_as_ushort(b) << 16);
}

// prep: split wg into fp16 h/l globals AND zero me/ce/done (no memset nodes)
__global__ void prep_b_kernel(const float* __restrict__ wg) {
    int idx = blockIdx.x * blockDim.x + threadIdx.x;  // 0..131071
    if (idx < N_EXP) { g_me[idx] = 0.0f; g_ce[idx] = 0; }
    if (idx == 0) g_done = 0u;
    float4 v = ((const float4*)wg)[idx];
    float f[4] = {v.x, v.y, v.z, v.w};
    __half h[4], l[4];
#pragma unroll
    for (int q = 0; q < 4; q++) split2(f[q], h[q], l[q]);
    ((uint2*)g_Bh)[idx] = make_uint2(pack2h(h[0], h[1]), pack2h(h[2], h[3]));
    ((uint2*)g_Bl)[idx] = make_uint2(pack2h(l[0], l[1]), pack2h(l[2], l[3]));
}

// top-2: (v1,i1) >= (v2,i2); ties -> smaller index (jax top_k semantics)
__device__ __forceinline__ void top2_upd(float& v1, int& i1, float& v2, int& i2,
                                         float v, int i) {
    if (v > v1 || (v == v1 && i < i1)) {
        v2 = v1; i2 = i1; v1 = v; i1 = i;
    } else if (v > v2 || (v == v2 && i < i2)) {
        v2 = v; i2 = i;
    }
}

__global__ void __launch_bounds__(TPB, 1)
gate_kernel(const float* __restrict__ A, float* __restrict__ out) {
    extern __shared__ char smem[];
    const uint32_t smem_u = smem_to_u32(smem);
    const int tid  = threadIdx.x;
    const int wid  = tid >> 5;
    const int lane = tid & 31;
    const int row0 = blockIdx.x * BM;

    float    acc[2][4][4];    // hh product, f32
    uint32_t accr[2][4][2];   // residual products, f16x2 pairs

    if (wid < 16) {
        // ================= CONSUMERS: 4(M) x 4(N) warp grid =================
        const int mw = wid >> 2;
        const int nw = wid & 3;
        const int a_mrow = (lane & 7) + ((lane >> 3) & 1) * 8;
        const int a_cofs = ((lane >> 4) & 1) * 16;
        const int b_nrow = (lane & 7) + ((lane >> 4) & 1) * 8;
        const int b_cofs = ((lane >> 3) & 1) * 16;

#pragma unroll
        for (int i = 0; i < 2; i++)
#pragma unroll
            for (int j = 0; j < 4; j++) {
#pragma unroll
                for (int q = 0; q < 4; q++) acc[i][j][q] = 0.0f;
                accr[i][j][0] = 0u; accr[i][j][1] = 0u;
            }

        for (int c = 0; c < NCHUNK; c++) {
            const int s = c & 1;
            const uint32_t cur = smem_u + s * STAGE_BYTES;
            BAR_SYNC(s == 0 ? BAR_FULL0 : BAR_FULL1);

#pragma unroll 1
            for (int ks = 0; ks < 4; ks++) {
                const int kb = ks * 32;
                uint32_t bfh[8], bfl[8];
#pragma unroll
                for (int q = 0; q < 2; q++) {
                    uint32_t bsw = SWZ((uint32_t)((nw * 32 + q * 16 + b_nrow) * 128 + kb + b_cofs));
                    LDSM4(bfh[q*4+0], bfh[q*4+1], bfh[q*4+2], bfh[q*4+3], cur + OFF_BH + bsw);
                    LDSM4(bfl[q*4+0], bfl[q*4+1], bfl[q*4+2], bfl[q*4+3], cur + OFF_BL + bsw);
                }
                uint32_t af[8];
#pragma unroll
                for (int tm = 0; tm < 2; tm++) {
                    uint32_t asw = SWZ((uint32_t)((mw * 32 + tm * 16 + a_mrow) * 128 + kb + a_cofs));
                    LDSM4(af[tm*4+0], af[tm*4+1], af[tm*4+2], af[tm*4+3], cur + OFF_AH + asw);
                }
#pragma unroll
                for (int tm = 0; tm < 2; tm++)
#pragma unroll
                    for (int tn = 0; tn < 4; tn++) {
                        int bq = (tn >> 1) * 4 + (tn & 1) * 2;
                        MMA16816(acc[tm][tn], &af[tm*4], bfh[bq], bfh[bq+1]);
                        MMA16816_H(accr[tm][tn], &af[tm*4], bfl[bq], bfl[bq+1]);
                    }
#pragma unroll
                for (int tm = 0; tm < 2; tm++) {
                    uint32_t asw = SWZ((uint32_t)((mw * 32 + tm * 16 + a_mrow) * 128 + kb + a_cofs));
                    LDSM4(af[tm*4+0], af[tm*4+1], af[tm*4+2], af[tm*4+3], cur + OFF_AL + asw);
                }
#pragma unroll
                for (int tm = 0; tm < 2; tm++)
#pragma unroll
                    for (int tn = 0; tn < 4; tn++) {
                        int bq = (tn >> 1) * 4 + (tn & 1) * 2;
                        MMA16816_H(accr[tm][tn], &af[tm*4], bfh[bq], bfh[bq+1]);
                    }
            }
            BAR_ARRIVE(s == 0 ? BAR_EMPTY0 : BAR_EMPTY1);
        }
    } else {
        // ================= PRODUCERS: 4 warps, 128 threads =================
        const int ptid = tid - 512;   // 0..127
        for (int c = 0; c < NCHUNK; c++) {
            const int s = c & 1;
            char* stg = smem + s * STAGE_BYTES;
            const uint32_t stg_u = smem_u + s * STAGE_BYTES;
            const int k0 = c * CK;

            if (c >= 2) BAR_SYNC(s == 0 ? BAR_EMPTY0 : BAR_EMPTY1);

            // B tiles via cp.async (in flight during A work)
#pragma unroll
            for (int i = 0; i < 8; i++) {
                int idx = ptid + i * 128;          // 0..1023
                int r   = idx >> 3;
                int c16 = (idx & 7) * 16;
                size_t g = (size_t)r * D_MODEL + k0 + (c16 >> 1);
                uint32_t sw = SWZ((uint32_t)(r * 128 + c16));
                cp16(stg_u + OFF_BH + sw, g_Bh + g);
                cp16(stg_u + OFF_BL + sw, g_Bl + g);
            }
            CP_COMMIT();

            // A: LDG -> split2 -> STS, 2 batches of 8 float4 (reg budget 102)
#pragma unroll
            for (int bat = 0; bat < 2; bat++) {
                float4 aval[8];
#pragma unroll
                for (int i = 0; i < 8; i++) {
                    int idx = ptid + (bat * 8 + i) * 128;   // 0..2047
                    int r   = idx >> 4;
                    int col = (idx & 15) << 2;
                    aval[i] = *(const float4*)(A + (size_t)(row0 + r) * D_MODEL + k0 + col);
                }
#pragma unroll
                for (int i = 0; i < 8; i++) {
                    int idx = ptid + (bat * 8 + i) * 128;
                    int r   = idx >> 4;
                    int col = (idx & 15) << 2;
                    float f[4] = {aval[i].x, aval[i].y, aval[i].z, aval[i].w};
                    __half h[4], l[4];
#pragma unroll
                    for (int q = 0; q < 4; q++) split2(f[q], h[q], l[q]);
                    uint32_t sw = SWZ((uint32_t)(r * 128 + col * 2));
                    *(uint2*)(stg + OFF_AH + sw) = make_uint2(pack2h(h[0], h[1]), pack2h(h[2], h[3]));
                    *(uint2*)(stg + OFF_AL + sw) = make_uint2(pack2h(l[0], l[1]), pack2h(l[2], l[3]));
                }
            }
            CP_WAIT0();
            BAR_ARRIVE(s == 0 ? BAR_FULL0 : BAR_FULL1);
        }
    }

    __syncthreads();   // all 640 threads; stages now free -> repurpose as Ls

    float* Ls  = (float*)smem;
    float* sMe = (float*)(smem + BM * LS_STRIDE * 4);

    if (wid < 16) {
        const int mw = wid >> 2, nw = wid & 3;
        const int gid = lane >> 2, tig = lane & 3;
#pragma unroll
        for (int tm = 0; tm < 2; tm++)
#pragma unroll
            for (int tn = 0; tn < 4; tn++) {
                float2 rlo = __half22float2(*(__half2*)&accr[tm][tn][0]);
                float2 rhi = __half22float2(*(__half2*)&accr[tm][tn][1]);
                int r_ = mw * 32 + tm * 16 + gid;
                int c_ = nw * 32 + tn * 8 + tig * 2;
                Ls[r_ * LS_STRIDE + c_]           = acc[tm][tn][0] + rlo.x;
                Ls[r_ * LS_STRIDE + c_ + 1]       = acc[tm][tn][1] + rlo.y;
                Ls[(r_ + 8) * LS_STRIDE + c_]     = acc[tm][tn][2] + rhi.x;
                Ls[(r_ + 8) * LS_STRIDE + c_ + 1] = acc[tm][tn][3] + rhi.y;
            }
    }
    if (tid >= 512 && tid < 512 + N_EXP) sMe[tid - 512] = 0.0f;
    __syncthreads();

    // ---- epilogue: one warp per token, 20 warps stride over 128 tokens ----
    const float inv_temp = 1.0f / 0.3f;
    for (int t = wid; t < BM; t += 20) {
        float v[4]; int ix[4];
#pragma unroll
        for (int q = 0; q < 4; q++) {
            ix[q] = lane + q * 32;
            v[q]  = Ls[t * LS_STRIDE + ix[q]];
        }
        float v1 = -INFINITY, v2 = -INFINITY;
        int   i1 = N_EXP, i2 = N_EXP;
#pragma unroll
        for (int q = 0; q < 4; q++) top2_upd(v1, i1, v2, i2, v[q], ix[q]);
#pragma unroll
        for (int off = 16; off > 0; off >>= 1) {
            float ov1 = __shfl_xor_sync(0xffffffffu, v1, off);
            int   oi1 = __shfl_xor_sync(0xffffffffu, i1, off);
            float ov2 = __shfl_xor_sync(0xffffffffu, v2, off);
            int   oi2 = __shfl_xor_sync(0xffffffffu, i2, off);
            top2_upd(v1, i1, v2, i2, ov1, oi1);
            top2_upd(v1, i1, v2, i2, ov2, oi2);
        }
        float p[4], zl = 0.0f;
#pragma unroll
        for (int q = 0; q < 4; q++) {
            p[q] = expf((v[q] - v1) * inv_temp);
            zl += p[q];
        }
#pragma unroll
        for (int off = 16; off > 0; off >>= 1)
            zl += __shfl_xor_sync(0xffffffffu, zl, off);
        float invZ = 1.0f / zl;
#pragma unroll
        for (int q = 0; q < 4; q++)
            atomicAdd(&sMe[ix[q]], p[q] * invZ);

        if (lane == 0) {
            int tok = row0 + t;
            out[tok * 2 + 0] = (float)i1;
            out[tok * 2 + 1] = (float)i2;
            float e  = expf(v2 - v1);
            float g1 = e / (1.0f + e);
            out[2 * T_TOKENS + tok * 2 + 0] = 1.0f - g1;
            out[2 * T_TOKENS + tok * 2 + 1] = g1;
            atomicAdd(&g_ce[i1], 1);
        }
    }
    __syncthreads();
    if (tid < N_EXP) atomicAdd(&g_me[tid], sMe[tid]);

    // ---- last-CTA loss reduction (replaces loss_kernel launch) ----
    __threadfence();
    __syncthreads();
    unsigned int* flag = (unsigned int*)smem;
    if (tid == 0) {
        unsigned int prev = atomicAdd(&g_done, 1u);
        *flag = (prev == gridDim.x - 1) ? 1u : 0u;
    }
    __syncthreads();
    if (*flag) {
        float* red = (float*)(smem + 64);
        if (tid < N_EXP)
            red[tid] = __ldcg(&g_me[tid]) * (float)__ldcg(&g_ce[tid]);
        __syncthreads();
        for (int s = 64; s > 0; s >>= 1) {
            if (tid < s) red[tid] += red[tid + s];
            __syncthreads();
        }
        if (tid == 0)
            out[4 * T_TOKENS] = red[0] * ((float)N_EXP /
                                  ((float)T_TOKENS * (float)T_TOKENS));
    }
}

extern "C" void kernel_launch(void* const* d_in, const int* in_sizes, int n_in,
                              void* d_out, int out_size) {
    const float* inp = (const float*)d_in[0];
    const float* wg  = (const float*)d_in[1];
    float* out = (float*)d_out;

    prep_b_kernel<<<(N_EXP * D_MODEL / 4 + 255) / 256, 256>>>(wg);

    cudaFuncSetAttribute(gate_kernel,
                         cudaFuncAttributeMaxDynamicSharedMemorySize,
                         SMEM_TOTAL);
    gate_kernel<<<T_TOKENS / BM, TPB, SMEM_TOTAL>>>(inp, out);
}